// round 5
// baseline (speedup 1.0000x reference)
#include <cuda_runtime.h>

#define NB 1024
#define NS 50
#define NH 64
#define NITEM 40000
#define TPB 256
#define NSPLIT 2              // compute CTAs per batch row (25 s each)
#define GROUP 7               // 2 compute + 5 zero per group
#define NZERO 5120
#define ZCHUNK 2000           // float4 per zero CTA: 5120*2000 = 10,240,000 exactly
#define SHALF 25

__device__ float g_scores[NB * NS];   // raw (pre-softmax) scores

__global__ __launch_bounds__(TPB, 2)
void fused_kernel(const float* __restrict__ all_memory,
                  const float* __restrict__ last_memory,
                  const float* __restrict__ Wr,
                  const float* __restrict__ Ur,
                  const float* __restrict__ Vr_w,
                  float* __restrict__ out)
{
    const int bid = blockIdx.x;
    const int grp = bid / GROUP;
    const int lane_in_grp = bid - grp * GROUP;
    const int tid = threadIdx.x;

    // ============== zero CTAs (5/7 of grid): pure store stream ==============
    if (lane_in_grp >= NSPLIT) {
        const int z = grp * 5 + (lane_in_grp - NSPLIT);   // 0..5119
        float4* p = reinterpret_cast<float4*>(out) + (size_t)z * ZCHUNK;
        const float4 zf = make_float4(0.f, 0.f, 0.f, 0.f);
        #pragma unroll
        for (int i = tid; i < ZCHUNK; i += TPB) p[i] = zf;
        return;
    }

    // ============== compute CTA: row b, s-half `half` =======================
    const int b    = grp;
    const int half = lane_in_grp;          // 0 or 1
    const int sbase = half * SHALF;

    __shared__ float xs[SHALF * NH];       // 6.4 KB  (25 s-rows)
    __shared__ float matW[NH * 65];        // 16.6 KB pad-65 conflict-free
    __shared__ float matU[NH * 65];        // 16.6 KB
    __shared__ float vals[SHALF * 68];     // 6.8 KB transpose buffer
    __shared__ float lastm[NH];

    const int k = tid & 63;
    const int g = tid >> 6;                // 0..3 (warp-uniform)

    // ---- stage (float4 loads, padded scalar stores) ----
    const float4* am4 = reinterpret_cast<const float4*>(
        all_memory + (size_t)b * (NS * NH) + sbase * NH);
    for (int i = tid; i < SHALF * NH / 4; i += TPB)
        reinterpret_cast<float4*>(xs)[i] = am4[i];
    if (tid < NH) lastm[tid] = last_memory[b * NH + tid];
    {
        const float4* w4 = reinterpret_cast<const float4*>(Wr);
        const float4* u4 = reinterpret_cast<const float4*>(Ur);
        for (int i = tid; i < NH * NH / 4; i += TPB) {
            int r = i >> 4, c = (i & 15) * 4;
            float4 w = w4[i], u = u4[i];
            float* dw = &matW[r * 65 + c];
            dw[0] = w.x; dw[1] = w.y; dw[2] = w.z; dw[3] = w.w;
            float* du = &matU[r * 65 + c];
            du[0] = u.x; du[1] = u.y; du[2] = u.z; du[3] = u.w;
        }
    }
    __syncthreads();

    // ---- lk = sum_h last[h]*Wr[k,h] (4 independent accumulators) ----
    float l0 = 0.f, l1 = 0.f, l2 = 0.f, l3 = 0.f;
    #pragma unroll
    for (int h = 0; h < NH; h += 4) {
        l0 += lastm[h]     * matW[k * 65 + h];
        l1 += lastm[h + 1] * matW[k * 65 + h + 1];
        l2 += lastm[h + 2] * matW[k * 65 + h + 2];
        l3 += lastm[h + 3] * matW[k * 65 + h + 3];
    }
    const float lk = (l0 + l1) + (l2 + l3);

    // ---- Ur row k into registers (pad-65 conflict-free) ----
    float ur[NH];
    #pragma unroll
    for (int h = 0; h < NH; h++) ur[h] = matU[k * 65 + h];
    const float vk = Vr_w[k];

    // ---- vals[sl][k] = vk * tanh(x[sl]·ur + lk), 7 iters (25 s-values) ----
    #pragma unroll
    for (int j = 0; j < 7; j++) {
        const int sl = 4 * j + g;                    // warp-uniform
        if (sl < SHALF) {
            const float4* xr = reinterpret_cast<const float4*>(xs + sl * NH);
            float a0 = lk, a1 = 0.f, a2 = 0.f, a3 = 0.f;
            #pragma unroll
            for (int i = 0; i < 16; i += 4) {
                float4 v0 = xr[i], v1 = xr[i + 1], v2 = xr[i + 2], v3 = xr[i + 3];
                a0 += v0.x*ur[4*i+ 0] + v0.y*ur[4*i+ 1] + v0.z*ur[4*i+ 2] + v0.w*ur[4*i+ 3];
                a1 += v1.x*ur[4*i+ 4] + v1.y*ur[4*i+ 5] + v1.z*ur[4*i+ 6] + v1.w*ur[4*i+ 7];
                a2 += v2.x*ur[4*i+ 8] + v2.y*ur[4*i+ 9] + v2.z*ur[4*i+10] + v2.w*ur[4*i+11];
                a3 += v3.x*ur[4*i+12] + v3.y*ur[4*i+13] + v3.z*ur[4*i+14] + v3.w*ur[4*i+15];
            }
            float acc = (a0 + a1) + (a2 + a3);
            // fast tanh: 1 - 2/(e^{2x}+1); saturates correctly
            float e2x = __expf(2.0f * acc);
            vals[sl * 68 + k] = vk * (1.0f - __fdividef(2.0f, e2x + 1.0f));
        }
    }
    __syncthreads();

    // ---- flat reduce over k: thread (sl,p) sums 16, quad-combine ----
    {
        const int sl = tid >> 2, p = tid & 3;        // sl: 0..63, p: 0..3
        if (sl < SHALF) {
            const float4* vr = reinterpret_cast<const float4*>(vals + sl * 68 + p * 16);
            float4 r0 = vr[0], r1 = vr[1], r2 = vr[2], r3 = vr[3];
            float sum = ((r0.x + r0.y) + (r0.z + r0.w)) + ((r1.x + r1.y) + (r1.z + r1.w))
                      + ((r2.x + r2.y) + (r2.z + r2.w)) + ((r3.x + r3.y) + (r3.z + r3.w));
            sum += __shfl_xor_sync(0xffffffffu, sum, 1);
            sum += __shfl_xor_sync(0xffffffffu, sum, 2);
            if (p == 0) g_scores[b * NS + sbase + sl] = sum;
        }
    }
}

// ============ Kernel 2: softmax + scatter-add per row ============
__global__ __launch_bounds__(64)
void softmax_scatter_kernel(const int* __restrict__ seq_item,
                            float* __restrict__ out)
{
    __shared__ float probs[64];
    const int b = blockIdx.x;
    const int t = threadIdx.x;

    if (t < 32) {
        float v0 = (t      < NS) ? g_scores[b * NS + t]      : -1e30f;
        float v1 = (t + 32 < NS) ? g_scores[b * NS + t + 32] : -1e30f;
        float m = fmaxf(v0, v1);
        #pragma unroll
        for (int o = 16; o; o >>= 1)
            m = fmaxf(m, __shfl_xor_sync(0xffffffffu, m, o));
        float e0 = (t      < NS) ? __expf(v0 - m) : 0.f;
        float e1 = (t + 32 < NS) ? __expf(v1 - m) : 0.f;
        float ssum = e0 + e1;
        #pragma unroll
        for (int o = 16; o; o >>= 1)
            ssum += __shfl_xor_sync(0xffffffffu, ssum, o);
        float inv = 1.f / ssum;
        probs[t]      = e0 * inv;
        probs[t + 32] = e1 * inv;
    }
    __syncthreads();

    if (t < NS) {
        int item = seq_item[b * NS + t];
        atomicAdd(out + (size_t)b * NITEM + item, probs[t]);
    }
}

extern "C" void kernel_launch(void* const* d_in, const int* in_sizes, int n_in,
                              void* d_out, int out_size)
{
    const float* all_memory  = (const float*)d_in[0];
    const float* last_memory = (const float*)d_in[1];
    const int*   seq_item    = (const int*)  d_in[2];
    const float* Wr          = (const float*)d_in[3];
    const float* Ur          = (const float*)d_in[4];
    const float* Vr_w        = (const float*)d_in[5];
    // d_in[6] = Vr_b — softmax shift-invariant, unused.
    float* out = (float*)d_out;

    fused_kernel<<<NB * GROUP, TPB>>>(all_memory, last_memory, Wr, Ur, Vr_w, out);
    softmax_scatter_kernel<<<NB, 64>>>(seq_item, out);
}

// round 7
// speedup vs baseline: 1.1058x; 1.1058x over previous
#include <cuda_runtime.h>

#define NB 1024
#define NS 50
#define NH 64
#define NITEM 40000
#define TPB 256
#define STRIDE 6          // 1 compute CTA per 5 zero CTAs (R4 proven layout)
#define ZCHUNK 2000       // float4 per zero CTA: 5120*2000 = 10,240,000 exactly

typedef unsigned long long u64;

__device__ __forceinline__ u64 pk(float lo, float hi) {
    u64 r; asm("mov.b64 %0, {%1, %2};" : "=l"(r) : "f"(lo), "f"(hi)); return r;
}
__device__ __forceinline__ void fma2(u64& d, u64 a, u64 b) {
    asm("fma.rn.f32x2 %0, %1, %2, %0;" : "+l"(d) : "l"(a), "l"(b));
}
__device__ __forceinline__ void add2(u64& d, u64 a) {
    asm("add.rn.f32x2 %0, %1, %0;" : "+l"(d) : "l"(a));
}
__device__ __forceinline__ float hsum2(u64 v) {
    float lo, hi; asm("mov.b64 {%0, %1}, %2;" : "=f"(lo), "=f"(hi) : "l"(v));
    return lo + hi;
}

__device__ float g_probs[NB * NS];   // probs scratch between kernels

__global__ __launch_bounds__(TPB, 2)
void fused_kernel(const float* __restrict__ all_memory,
                  const float* __restrict__ last_memory,
                  const float* __restrict__ Wr,
                  const float* __restrict__ Ur,
                  const float* __restrict__ Vr_w,
                  float* __restrict__ out)
{
    const int bid = blockIdx.x;
    const int q   = bid / STRIDE;
    const int tid = threadIdx.x;

    // ================= zero CTAs (5/6 of grid): pure store stream =========
    if (bid - q * STRIDE != 0) {
        const int z = bid - q - 1;               // 0..5119
        float4* p = reinterpret_cast<float4*>(out) + (size_t)z * ZCHUNK;
        const float4 zf = make_float4(0.f, 0.f, 0.f, 0.f);
        #pragma unroll
        for (int i = tid; i < ZCHUNK; i += TPB) p[i] = zf;
        return;
    }

    // ================= compute CTA: one batch row b = q ====================
    const int b = q;

    __shared__ __align__(16) float xs[NS * NH];  // 12.8 KB
    __shared__ float matW[NH * 65];              // 16.6 KB, pad-65 conflict-free
    __shared__ float matU[NH * 65];              // 16.6 KB
    __shared__ __align__(16) float vals[64 * 68];// 17.4 KB transpose buffer
    __shared__ float lastm[NH];
    __shared__ float scores[64];

    const int k = tid & 63;
    const int g = tid >> 6;              // 0..3 (warp-uniform)

    // ---- stage (float4 loads, scalar padded stores) ----
    const float4* am4 = reinterpret_cast<const float4*>(all_memory + (size_t)b * (NS * NH));
    for (int i = tid; i < NS * NH / 4; i += TPB)
        reinterpret_cast<float4*>(xs)[i] = am4[i];
    if (tid < NH) lastm[tid] = last_memory[b * NH + tid];
    {
        const float4* w4 = reinterpret_cast<const float4*>(Wr);
        const float4* u4 = reinterpret_cast<const float4*>(Ur);
        for (int i = tid; i < NH * NH / 4; i += TPB) {
            int r = i >> 4, c = (i & 15) * 4;
            float4 w = w4[i], u = u4[i];
            float* dw = &matW[r * 65 + c];
            dw[0] = w.x; dw[1] = w.y; dw[2] = w.z; dw[3] = w.w;
            float* du = &matU[r * 65 + c];
            du[0] = u.x; du[1] = u.y; du[2] = u.z; du[3] = u.w;
        }
    }
    __syncthreads();

    // ---- lk = sum_h last[h]*Wr[k,h] (once; scalar FMA is fine here) ----
    float l0 = 0.f, l1 = 0.f, l2 = 0.f, l3 = 0.f;
    #pragma unroll
    for (int h = 0; h < NH; h += 4) {
        l0 += lastm[h]     * matW[k * 65 + h];
        l1 += lastm[h + 1] * matW[k * 65 + h + 1];
        l2 += lastm[h + 2] * matW[k * 65 + h + 2];
        l3 += lastm[h + 3] * matW[k * 65 + h + 3];
    }
    const float lk = (l0 + l1) + (l2 + l3);

    // ---- Ur row k packed into 32 x f32x2 registers (pad-65 conflict-free) ----
    u64 urp[NH / 2];
    #pragma unroll
    for (int h = 0; h < NH / 2; h++)
        urp[h] = pk(matU[k * 65 + 2 * h], matU[k * 65 + 2 * h + 1]);
    const float vk = Vr_w[k];

    // ---- vals[s][k] = vk * tanh(x[s].ur + lk); packed f32x2 FMA ----
    #pragma unroll
    for (int j = 0; j < 13; j++) {
        const int s = 4 * j + g;                 // warp-uniform
        if (s < NS) {
            // xr[i] = floats [4i .. 4i+3] = packed u64 pair {urp idx 2i, 2i+1}
            const ulonglong2* xr = reinterpret_cast<const ulonglong2*>(xs + s * NH);
            u64 a0 = pk(lk, 0.f), a1 = pk(0.f, 0.f), a2 = pk(0.f, 0.f), a3 = pk(0.f, 0.f);
            #pragma unroll
            for (int i = 0; i < 16; i += 2) {    // 16 ulonglong2 = 64 floats
                ulonglong2 w0 = xr[i], w1 = xr[i + 1];
                fma2(a0, w0.x, urp[2 * i]);
                fma2(a1, w0.y, urp[2 * i + 1]);
                fma2(a2, w1.x, urp[2 * i + 2]);
                fma2(a3, w1.y, urp[2 * i + 3]);
            }
            add2(a0, a1); add2(a2, a3); add2(a0, a2);
            float acc = hsum2(a0);
            // fast tanh: 1 - 2/(e^{2x}+1); saturates correctly
            float e2x = __expf(2.0f * acc);
            vals[s * 68 + k] = vk * (1.0f - __fdividef(2.0f, e2x + 1.0f));
        }
    }
    __syncthreads();

    // ---- flat reduction over k: thread (s2,p) sums 16, quad-combine ----
    {
        const int s2 = tid >> 2, p = tid & 3;    // s2: 0..63, p: 0..3
        const float4* vr = reinterpret_cast<const float4*>(vals + s2 * 68 + p * 16);
        float4 r0 = vr[0], r1 = vr[1], r2 = vr[2], r3 = vr[3];
        float sum = ((r0.x + r0.y) + (r0.z + r0.w)) + ((r1.x + r1.y) + (r1.z + r1.w))
                  + ((r2.x + r2.y) + (r2.z + r2.w)) + ((r3.x + r3.y) + (r3.z + r3.w));
        sum += __shfl_xor_sync(0xffffffffu, sum, 1);
        sum += __shfl_xor_sync(0xffffffffu, sum, 2);
        if (p == 0 && s2 < NS) scores[s2] = sum;
    }
    __syncthreads();

    // ---- softmax over S=50 (warp 0); Vr_b cancels; write probs scratch ----
    if (tid < 32) {
        float v0 = (tid      < NS) ? scores[tid]      : -1e30f;
        float v1 = (tid + 32 < NS) ? scores[tid + 32] : -1e30f;
        float m = fmaxf(v0, v1);
        #pragma unroll
        for (int o = 16; o; o >>= 1)
            m = fmaxf(m, __shfl_xor_sync(0xffffffffu, m, o));
        float e0 = (tid      < NS) ? __expf(v0 - m) : 0.f;
        float e1 = (tid + 32 < NS) ? __expf(v1 - m) : 0.f;
        float ssum = e0 + e1;
        #pragma unroll
        for (int o = 16; o; o >>= 1)
            ssum += __shfl_xor_sync(0xffffffffu, ssum, o);
        float inv = 1.f / ssum;
        if (tid      < NS) g_probs[b * NS + tid]      = e0 * inv;
        if (tid + 32 < NS) g_probs[b * NS + tid + 32] = e1 * inv;
    }
}

// ============ Kernel 2: scatter-add probs into zeroed output ============
__global__ __launch_bounds__(64)
void scatter_kernel(const int* __restrict__ seq_item, float* __restrict__ out)
{
    const int b = blockIdx.x;
    const int t = threadIdx.x;
    if (t < NS) {
        int item = seq_item[b * NS + t];
        atomicAdd(out + (size_t)b * NITEM + item, g_probs[b * NS + t]);
    }
}

extern "C" void kernel_launch(void* const* d_in, const int* in_sizes, int n_in,
                              void* d_out, int out_size)
{
    const float* all_memory  = (const float*)d_in[0];
    const float* last_memory = (const float*)d_in[1];
    const int*   seq_item    = (const int*)  d_in[2];
    const float* Wr          = (const float*)d_in[3];
    const float* Ur          = (const float*)d_in[4];
    const float* Vr_w        = (const float*)d_in[5];
    // d_in[6] = Vr_b — softmax shift-invariant, unused.
    float* out = (float*)d_out;

    fused_kernel<<<NB * STRIDE, TPB>>>(all_memory, last_memory, Wr, Ur, Vr_w, out);
    scatter_kernel<<<NB, 64>>>(seq_item, out);
}

// round 9
// speedup vs baseline: 1.1588x; 1.0479x over previous
#include <cuda_runtime.h>

#define NB 1024
#define NS 50
#define NH 64
#define NITEM 40000
#define TPB 256
#define GROUP 11          // 1 compute CTA (2 rows) + 10 zero CTAs
#define NQ (NB / 2)       // 512 compute CTAs
#define ZCHUNK 2000       // float4 per zero CTA: 5120*2000 = 10,240,000 exactly

typedef unsigned long long u64;

__device__ __forceinline__ u64 pk(float lo, float hi) {
    u64 r; asm("mov.b64 %0, {%1, %2};" : "=l"(r) : "f"(lo), "f"(hi)); return r;
}
__device__ __forceinline__ void fma2(u64& d, u64 a, u64 b) {
    asm("fma.rn.f32x2 %0, %1, %2, %0;" : "+l"(d) : "l"(a), "l"(b));
}
__device__ __forceinline__ void add2(u64& d, u64 a) {
    asm("add.rn.f32x2 %0, %1, %0;" : "+l"(d) : "l"(a));
}
__device__ __forceinline__ float hsum2(u64 v) {
    float lo, hi; asm("mov.b64 {%0, %1}, %2;" : "=f"(lo), "=f"(hi) : "l"(v));
    return lo + hi;
}

__device__ float g_probs[NB * NS];   // probs scratch between kernels

__global__ __launch_bounds__(TPB, 2)
void fused_kernel(const float* __restrict__ all_memory,
                  const float* __restrict__ last_memory,
                  const float* __restrict__ Wr,
                  const float* __restrict__ Ur,
                  const float* __restrict__ Vr_w,
                  float* __restrict__ out)
{
    const int bid = blockIdx.x;
    const int q   = bid / GROUP;
    const int lane_in_grp = bid - q * GROUP;
    const int tid = threadIdx.x;

    // ================= zero CTAs (10/11 of grid): pure store stream =========
    if (lane_in_grp != 0) {
        const int z = q * 10 + (lane_in_grp - 1);        // 0..5119
        float4* p = reinterpret_cast<float4*>(out) + (size_t)z * ZCHUNK;
        const float4 zf = make_float4(0.f, 0.f, 0.f, 0.f);
        #pragma unroll
        for (int i = tid; i < ZCHUNK; i += TPB) p[i] = zf;
        return;
    }

    // ============ compute CTA: rows b0 = 2q, b1 = 2q+1 =====================
    const int b0 = 2 * q;

    __shared__ __align__(16) float xs[2 * NS * NH];   // 25.6 KB (both rows, contiguous)
    __shared__ float matW[NH * 65];                   // 16.6 KB pad-65 conflict-free
    __shared__ float matU[NH * 65];                   // 16.6 KB
    __shared__ __align__(16) float vals[2][NS * 68];  // 27.2 KB transpose buffers
    __shared__ float lastm[2][NH];
    __shared__ float scores[2][64];

    const int k = tid & 63;
    const int g = tid >> 6;              // 0..3 (warp-uniform)

    // ---- stage (rows 2q and 2q+1 are contiguous in all_memory) ----
    const float4* am4 = reinterpret_cast<const float4*>(all_memory + (size_t)b0 * (NS * NH));
    for (int i = tid; i < 2 * NS * NH / 4; i += TPB)
        reinterpret_cast<float4*>(xs)[i] = am4[i];
    if (tid < 2 * NH) lastm[tid >> 6][tid & 63] = last_memory[b0 * NH + tid];
    {
        const float4* w4 = reinterpret_cast<const float4*>(Wr);
        const float4* u4 = reinterpret_cast<const float4*>(Ur);
        for (int i = tid; i < NH * NH / 4; i += TPB) {
            int r = i >> 4, c = (i & 15) * 4;
            float4 w = w4[i], u = u4[i];
            float* dw = &matW[r * 65 + c];
            dw[0] = w.x; dw[1] = w.y; dw[2] = w.z; dw[3] = w.w;
            float* du = &matU[r * 65 + c];
            du[0] = u.x; du[1] = u.y; du[2] = u.z; du[3] = u.w;
        }
    }
    __syncthreads();

    // ---- lk[r] = sum_h last[r][h]*Wr[k,h] ----
    float lkA0 = 0.f, lkA1 = 0.f, lkB0 = 0.f, lkB1 = 0.f;
    #pragma unroll
    for (int h = 0; h < NH; h += 2) {
        float w0 = matW[k * 65 + h], w1 = matW[k * 65 + h + 1];
        lkA0 += lastm[0][h] * w0;  lkA1 += lastm[0][h + 1] * w1;
        lkB0 += lastm[1][h] * w0;  lkB1 += lastm[1][h + 1] * w1;
    }
    const float lk0 = lkA0 + lkA1;
    const float lk1 = lkB0 + lkB1;

    // ---- Ur row k packed into 32 x f32x2 registers (reused for BOTH rows) ----
    u64 urp[NH / 2];
    #pragma unroll
    for (int h = 0; h < NH / 2; h++)
        urp[h] = pk(matU[k * 65 + 2 * h], matU[k * 65 + 2 * h + 1]);
    const float vk = Vr_w[k];

    // ---- main loop: both rows interleaved for ILP ----
    #pragma unroll
    for (int j = 0; j < 13; j++) {
        const int s = 4 * j + g;                     // warp-uniform
        if (s < NS) {
            const ulonglong2* xrA = reinterpret_cast<const ulonglong2*>(xs + s * NH);
            const ulonglong2* xrB = reinterpret_cast<const ulonglong2*>(xs + (NS + s) * NH);
            u64 a0 = pk(lk0, 0.f), a1 = pk(0.f, 0.f);
            u64 c0 = pk(lk1, 0.f), c1 = pk(0.f, 0.f);
            #pragma unroll
            for (int i = 0; i < 16; i++) {           // 16 ulonglong2 = 64 floats
                ulonglong2 wA = xrA[i], wB = xrB[i];
                fma2(a0, wA.x, urp[2 * i]);
                fma2(c0, wB.x, urp[2 * i]);
                fma2(a1, wA.y, urp[2 * i + 1]);
                fma2(c1, wB.y, urp[2 * i + 1]);
            }
            add2(a0, a1); add2(c0, c1);
            float accA = hsum2(a0), accB = hsum2(c0);
            // fast tanh: 1 - 2/(e^{2x}+1)
            float eA = __expf(2.0f * accA), eB = __expf(2.0f * accB);
            vals[0][s * 68 + k] = vk * (1.0f - __fdividef(2.0f, eA + 1.0f));
            vals[1][s * 68 + k] = vk * (1.0f - __fdividef(2.0f, eB + 1.0f));
        }
    }
    __syncthreads();

    // ---- flat reduction over k, both rows ----
    // CLAMP (not guard): every lane of every warp executes the shuffles —
    // guarding the shfl on s2<NS deadlocks warps that straddle s2=50 (R8 bug).
    {
        const int s2 = tid >> 2, p = tid & 3;        // s2: 0..63, p: 0..3
        const int s2c = (s2 < NS) ? s2 : (NS - 1);   // in-bounds dummy for s2>=50
        #pragma unroll
        for (int r = 0; r < 2; r++) {
            const float4* vr = reinterpret_cast<const float4*>(&vals[r][s2c * 68 + p * 16]);
            float4 r0 = vr[0], r1 = vr[1], r2 = vr[2], r3 = vr[3];
            float sum = ((r0.x + r0.y) + (r0.z + r0.w)) + ((r1.x + r1.y) + (r1.z + r1.w))
                      + ((r2.x + r2.y) + (r2.z + r2.w)) + ((r3.x + r3.y) + (r3.z + r3.w));
            sum += __shfl_xor_sync(0xffffffffu, sum, 1);
            sum += __shfl_xor_sync(0xffffffffu, sum, 2);
            if (p == 0 && s2 < NS) scores[r][s2] = sum;
        }
    }
    __syncthreads();

    // ---- softmax: warp 0 -> row 0, warp 1 -> row 1 ----
    if (tid < 64) {
        const int r = tid >> 5;                      // row
        const int t = tid & 31;
        float v0 = (t      < NS) ? scores[r][t]      : -1e30f;
        float v1 = (t + 32 < NS) ? scores[r][t + 32] : -1e30f;
        float m = fmaxf(v0, v1);
        #pragma unroll
        for (int o = 16; o; o >>= 1)
            m = fmaxf(m, __shfl_xor_sync(0xffffffffu, m, o));
        float e0 = (t      < NS) ? __expf(v0 - m) : 0.f;
        float e1 = (t + 32 < NS) ? __expf(v1 - m) : 0.f;
        float ssum = e0 + e1;
        #pragma unroll
        for (int o = 16; o; o >>= 1)
            ssum += __shfl_xor_sync(0xffffffffu, ssum, o);
        float inv = 1.f / ssum;
        if (t      < NS) g_probs[(b0 + r) * NS + t]      = e0 * inv;
        if (t + 32 < NS) g_probs[(b0 + r) * NS + t + 32] = e1 * inv;
    }
}

// ============ Kernel 2: scatter-add probs into zeroed output ============
__global__ __launch_bounds__(64)
void scatter_kernel(const int* __restrict__ seq_item, float* __restrict__ out)
{
    const int b = blockIdx.x;
    const int t = threadIdx.x;
    if (t < NS) {
        int item = seq_item[b * NS + t];
        atomicAdd(out + (size_t)b * NITEM + item, g_probs[b * NS + t]);
    }
}

extern "C" void kernel_launch(void* const* d_in, const int* in_sizes, int n_in,
                              void* d_out, int out_size)
{
    const float* all_memory  = (const float*)d_in[0];
    const float* last_memory = (const float*)d_in[1];
    const int*   seq_item    = (const int*)  d_in[2];
    const float* Wr          = (const float*)d_in[3];
    const float* Ur          = (const float*)d_in[4];
    const float* Vr_w        = (const float*)d_in[5];
    // d_in[6] = Vr_b — softmax shift-invariant, unused.
    float* out = (float*)d_out;

    fused_kernel<<<NQ * GROUP, TPB>>>(all_memory, last_memory, Wr, Ur, Vr_w, out);
    scatter_kernel<<<NB, 64>>>(seq_item, out);
}

// round 10
// speedup vs baseline: 1.3533x; 1.1679x over previous
#include <cuda_runtime.h>

#define NB 1024
#define NS 50
#define NH 64
#define NITEM 40000
#define TPB 256
#define NQ (NB / 2)       // 512 CTAs, 2 rows each

typedef unsigned long long u64;

__device__ __forceinline__ u64 pk(float lo, float hi) {
    u64 r; asm("mov.b64 %0, {%1, %2};" : "=l"(r) : "f"(lo), "f"(hi)); return r;
}
__device__ __forceinline__ void fma2(u64& d, u64 a, u64 b) {
    asm("fma.rn.f32x2 %0, %1, %2, %0;" : "+l"(d) : "l"(a), "l"(b));
}
__device__ __forceinline__ void add2(u64& d, u64 a) {
    asm("add.rn.f32x2 %0, %1, %0;" : "+l"(d) : "l"(a));
}
__device__ __forceinline__ float hsum2(u64 v) {
    float lo, hi; asm("mov.b64 {%0, %1}, %2;" : "=f"(lo), "=f"(hi) : "l"(v));
    return lo + hi;
}

__global__ __launch_bounds__(TPB, 2)
void rrd_all(const float* __restrict__ all_memory,
             const float* __restrict__ last_memory,
             const int*   __restrict__ seq_item,
             const float* __restrict__ Wr,
             const float* __restrict__ Ur,
             const float* __restrict__ Vr_w,
             float* __restrict__ out)
{
    const int q   = blockIdx.x;
    const int b0  = 2 * q;
    const int tid = threadIdx.x;

    __shared__ __align__(16) float xs[2 * NS * NH];   // 25.6 KB
    __shared__ float matW[NH * 65];                   // 16.6 KB pad-65
    __shared__ float matU[NH * 65];                   // 16.6 KB
    __shared__ __align__(16) float vals[2][NS * 68];  // 27.2 KB
    __shared__ float lastm[2][NH];
    __shared__ float scores[2][64];
    __shared__ float probs[2][NS];

    // ---- stage (all 256 threads; rows 2q,2q+1 contiguous) ----
    const float4* am4 = reinterpret_cast<const float4*>(all_memory + (size_t)b0 * (NS * NH));
    for (int i = tid; i < 2 * NS * NH / 4; i += TPB)
        reinterpret_cast<float4*>(xs)[i] = am4[i];
    if (tid < 2 * NH) lastm[tid >> 6][tid & 63] = last_memory[b0 * NH + tid];
    {
        const float4* w4 = reinterpret_cast<const float4*>(Wr);
        const float4* u4 = reinterpret_cast<const float4*>(Ur);
        for (int i = tid; i < NH * NH / 4; i += TPB) {
            int r = i >> 4, c = (i & 15) * 4;
            float4 w = w4[i], u = u4[i];
            float* dw = &matW[r * 65 + c];
            dw[0] = w.x; dw[1] = w.y; dw[2] = w.z; dw[3] = w.w;
            float* du = &matU[r * 65 + c];
            du[0] = u.x; du[1] = u.y; du[2] = u.z; du[3] = u.w;
        }
    }
    __syncthreads();

    float* rowbase = out + (size_t)b0 * NITEM;

    if (tid < 192) {
        // ============ compute warps 0-5: score loop for both rows ============
        const int k = tid & 63;
        const int g = tid >> 6;          // 0..2 (warp-uniform)

        // lk[r] = sum_h last[r][h]*Wr[k,h]
        float lkA0 = 0.f, lkA1 = 0.f, lkB0 = 0.f, lkB1 = 0.f;
        #pragma unroll
        for (int h = 0; h < NH; h += 2) {
            float w0 = matW[k * 65 + h], w1 = matW[k * 65 + h + 1];
            lkA0 += lastm[0][h] * w0;  lkA1 += lastm[0][h + 1] * w1;
            lkB0 += lastm[1][h] * w0;  lkB1 += lastm[1][h + 1] * w1;
        }
        const float lk0 = lkA0 + lkA1;
        const float lk1 = lkB0 + lkB1;

        // Ur row k packed (reused for both rows)
        u64 urp[NH / 2];
        #pragma unroll
        for (int h = 0; h < NH / 2; h++)
            urp[h] = pk(matU[k * 65 + 2 * h], matU[k * 65 + 2 * h + 1]);
        const float vk = Vr_w[k];

        #pragma unroll
        for (int j = 0; j < 17; j++) {
            const int s = 3 * j + g;                 // warp-uniform
            if (s < NS) {
                const ulonglong2* xrA = reinterpret_cast<const ulonglong2*>(xs + s * NH);
                const ulonglong2* xrB = reinterpret_cast<const ulonglong2*>(xs + (NS + s) * NH);
                u64 a0 = pk(lk0, 0.f), a1 = pk(0.f, 0.f);
                u64 c0 = pk(lk1, 0.f), c1 = pk(0.f, 0.f);
                #pragma unroll
                for (int i = 0; i < 16; i++) {
                    ulonglong2 wA = xrA[i], wB = xrB[i];
                    fma2(a0, wA.x, urp[2 * i]);
                    fma2(c0, wB.x, urp[2 * i]);
                    fma2(a1, wA.y, urp[2 * i + 1]);
                    fma2(c1, wB.y, urp[2 * i + 1]);
                }
                add2(a0, a1); add2(c0, c1);
                float accA = hsum2(a0), accB = hsum2(c0);
                float eA = __expf(2.0f * accA), eB = __expf(2.0f * accB);
                vals[0][s * 68 + k] = vk * (1.0f - __fdividef(2.0f, eA + 1.0f));
                vals[1][s * 68 + k] = vk * (1.0f - __fdividef(2.0f, eB + 1.0f));
            }
        }
    } else {
        // ============ zero warps 6-7: this CTA's own 2 output rows ============
        // 80000 floats = 20000 float4 across 64 threads (313 iters)
        float4* row4 = reinterpret_cast<float4*>(rowbase);
        const float4 zf = make_float4(0.f, 0.f, 0.f, 0.f);
        for (int i = tid - 192; i < (2 * NITEM) / 4; i += 64)
            row4[i] = zf;
    }
    __syncthreads();   // vals ready AND zero stores issued+CTA-fenced

    // ---- flat reduction over k (all 256 threads; clamped shuffles) ----
    {
        const int s2 = tid >> 2, p = tid & 3;
        const int s2c = (s2 < NS) ? s2 : (NS - 1);
        #pragma unroll
        for (int r = 0; r < 2; r++) {
            const float4* vr = reinterpret_cast<const float4*>(&vals[r][s2c * 68 + p * 16]);
            float4 r0 = vr[0], r1 = vr[1], r2 = vr[2], r3 = vr[3];
            float sum = ((r0.x + r0.y) + (r0.z + r0.w)) + ((r1.x + r1.y) + (r1.z + r1.w))
                      + ((r2.x + r2.y) + (r2.z + r2.w)) + ((r3.x + r3.y) + (r3.z + r3.w));
            sum += __shfl_xor_sync(0xffffffffu, sum, 1);
            sum += __shfl_xor_sync(0xffffffffu, sum, 2);
            if (p == 0 && s2 < NS) scores[r][s2] = sum;
        }
    }
    __syncthreads();

    // ---- softmax: warp 0 -> row 0, warp 1 -> row 1 (Vr_b cancels) ----
    if (tid < 64) {
        const int r = tid >> 5;
        const int t = tid & 31;
        float v0 = (t      < NS) ? scores[r][t]      : -1e30f;
        float v1 = (t + 32 < NS) ? scores[r][t + 32] : -1e30f;
        float m = fmaxf(v0, v1);
        #pragma unroll
        for (int o = 16; o; o >>= 1)
            m = fmaxf(m, __shfl_xor_sync(0xffffffffu, m, o));
        float e0 = (t      < NS) ? __expf(v0 - m) : 0.f;
        float e1 = (t + 32 < NS) ? __expf(v1 - m) : 0.f;
        float ssum = e0 + e1;
        #pragma unroll
        for (int o = 16; o; o >>= 1)
            ssum += __shfl_xor_sync(0xffffffffu, ssum, o);
        float inv = 1.f / ssum;
        if (t      < NS) probs[r][t]      = e0 * inv;
        if (t + 32 < NS) probs[r][t + 32] = e1 * inv;
    }
    __syncthreads();   // probs published; zeros ordered before atomics (CTA fence)

    // ---- scatter-add both rows (atomics handle duplicate items) ----
    if (tid < 2 * NS) {
        const int r = tid / NS, t = tid - r * NS;
        int item = seq_item[(b0 + r) * NS + t];
        atomicAdd(rowbase + (size_t)r * NITEM + item, probs[r][t]);
    }
}

extern "C" void kernel_launch(void* const* d_in, const int* in_sizes, int n_in,
                              void* d_out, int out_size)
{
    const float* all_memory  = (const float*)d_in[0];
    const float* last_memory = (const float*)d_in[1];
    const int*   seq_item    = (const int*)  d_in[2];
    const float* Wr          = (const float*)d_in[3];
    const float* Ur          = (const float*)d_in[4];
    const float* Vr_w        = (const float*)d_in[5];
    // d_in[6] = Vr_b — softmax shift-invariant, unused.
    float* out = (float*)d_out;

    rrd_all<<<NQ, TPB>>>(all_memory, last_memory, seq_item, Wr, Ur, Vr_w, out);
}